// round 1
// baseline (speedup 1.0000x reference)
#include <cuda_runtime.h>

// Problem constants (fixed by the reference)
#define NE   8       // experts
#define DD   512     // embed
#define NH   8       // heads
#define HD   64      // head dim
#define DFF  2048    // ffn hidden
#define NTOK 4096    // B*S

// ---------------- scratch (static device globals; no allocation) -------------
__device__ float g_hidden[(size_t)NE * NTOK * DFF]; // 256 MB
__device__ float g_eo    [(size_t)NE * NTOK * DD];  // 64 MB
__device__ float g_k     [(size_t)NE * NTOK * DD];  // 64 MB
__device__ float g_v     [(size_t)NE * NTOK * DD];  // 64 MB
__device__ float g_q     [(size_t)NTOK * DD];       // 8 MB  (only expert_id row)
__device__ float g_ctx   [(size_t)NTOK * DD];       // 8 MB

// ---------------- generic tiled SGEMM, fp32 with fma.rn.f32x2 ---------------
// C[M,N] = A[M,K] @ op(B) + bias, optional relu.
// TRANSB=false: B is [K,N] row-major. TRANSB=true: B is [N,K] row-major (W.T).
// blockIdx.z = batch; strides select per-batch slices. eidPtr (optional)
// offsets A by (*eidPtr)*eidStride at runtime (expert_id lives on device).
// Tiles: 128x128x8, 256 threads, 8x8 per thread (4+4 split layout).

template<bool TRANSB, bool RELU>
__global__ void sgemm_kernel(const float* __restrict__ Ag,
                             const float* __restrict__ Bg,
                             const float* __restrict__ biasg,
                             float* __restrict__ Cg,
                             int M, int N, int K,
                             size_t sA, size_t sB, size_t sBias, size_t sC,
                             const int* __restrict__ eidPtr, size_t eidStride)
{
    const int tid = threadIdx.x;
    const int e   = blockIdx.z;

    const float* A = Ag + (size_t)e * sA;
    if (eidPtr) A += (size_t)(*eidPtr) * eidStride;
    const float* B    = Bg + (size_t)e * sB;
    const float* bias = biasg + (size_t)e * sBias;
    float* C          = Cg + (size_t)e * sC;

    const int m0 = blockIdx.y * 128;
    const int n0 = blockIdx.x * 128;

    __shared__ __align__(16) float As[8][128];
    __shared__ __align__(16) float Bs[8][128];

    // compute-thread coordinates (4+4 split => conflict-free LDS.128)
    const int ry  = (tid >> 4) * 4;   // 0..60, row base within half-tile
    const int cxw = (tid & 15) * 4;   // 0..60, col base within half-tile

    // load-thread coordinates
    const int lm = tid >> 1;          // 0..127 (row of A, or row of B^T)
    const int lk = (tid & 1) * 4;     // 0 or 4 (k sub-offset, float4 along K)
    const int bn = (tid & 31) * 4;    // 0..124 (col of B, non-trans)
    const int bk = tid >> 5;          // 0..7   (k row of B, non-trans)

    unsigned long long acc[8][4];     // packed f32x2 accumulators (8 rows x 4 col-pairs)
    #pragma unroll
    for (int i = 0; i < 8; i++)
        #pragma unroll
        for (int j = 0; j < 4; j++) acc[i][j] = 0ull;  // {0.f,0.f}

    for (int k0 = 0; k0 < K; k0 += 8) {
        // ---- stage tile into shared ----
        float4 av = *(const float4*)&A[(size_t)(m0 + lm) * K + k0 + lk];
        As[lk + 0][lm] = av.x; As[lk + 1][lm] = av.y;
        As[lk + 2][lm] = av.z; As[lk + 3][lm] = av.w;

        if (TRANSB) {
            float4 bv4 = *(const float4*)&B[(size_t)(n0 + lm) * K + k0 + lk];
            Bs[lk + 0][lm] = bv4.x; Bs[lk + 1][lm] = bv4.y;
            Bs[lk + 2][lm] = bv4.z; Bs[lk + 3][lm] = bv4.w;
        } else {
            *(float4*)&Bs[bk][bn] = *(const float4*)&B[(size_t)(k0 + bk) * N + n0 + bn];
        }
        __syncthreads();

        // ---- compute ----
        #pragma unroll
        for (int kk = 0; kk < 8; kk++) {
            float a[8];
            *(float4*)(a + 0) = *(const float4*)&As[kk][ry];
            *(float4*)(a + 4) = *(const float4*)&As[kk][64 + ry];

            unsigned long long a2[8];
            #pragma unroll
            for (int i = 0; i < 8; i++)
                asm("mov.b64 %0, {%1,%1};" : "=l"(a2[i]) : "f"(a[i]));

            unsigned long long b2[4];
            {
                ulonglong2 t0 = *(const ulonglong2*)&Bs[kk][cxw];
                ulonglong2 t1 = *(const ulonglong2*)&Bs[kk][64 + cxw];
                b2[0] = t0.x; b2[1] = t0.y; b2[2] = t1.x; b2[3] = t1.y;
            }

            #pragma unroll
            for (int i = 0; i < 8; i++)
                #pragma unroll
                for (int j = 0; j < 4; j++)
                    asm("fma.rn.f32x2 %0, %1, %2, %0;"
                        : "+l"(acc[i][j]) : "l"(a2[i]), "l"(b2[j]));
        }
        __syncthreads();
    }

    // ---- epilogue: unpack, +bias, relu?, store ----
    const int c0 = n0 + cxw;
    const int c1 = n0 + 64 + cxw;
    const float4 bv0 = *(const float4*)&bias[c0];
    const float4 bv1 = *(const float4*)&bias[c1];

    #pragma unroll
    for (int i = 0; i < 8; i++) {
        const int r = m0 + ((i < 4) ? (ry + i) : (64 + ry + i - 4));
        float o[8];
        #pragma unroll
        for (int j = 0; j < 4; j++) {
            float lo, hi;
            asm("mov.b64 {%0,%1}, %2;" : "=f"(lo), "=f"(hi) : "l"(acc[i][j]));
            o[2 * j] = lo; o[2 * j + 1] = hi;
        }
        float4 v0 = { o[0] + bv0.x, o[1] + bv0.y, o[2] + bv0.z, o[3] + bv0.w };
        float4 v1 = { o[4] + bv1.x, o[5] + bv1.y, o[6] + bv1.z, o[7] + bv1.w };
        if (RELU) {
            v0.x = fmaxf(v0.x, 0.f); v0.y = fmaxf(v0.y, 0.f);
            v0.z = fmaxf(v0.z, 0.f); v0.w = fmaxf(v0.w, 0.f);
            v1.x = fmaxf(v1.x, 0.f); v1.y = fmaxf(v1.y, 0.f);
            v1.z = fmaxf(v1.z, 0.f); v1.w = fmaxf(v1.w, 0.f);
        }
        *(float4*)&C[(size_t)r * N + c0] = v0;
        *(float4*)&C[(size_t)r * N + c1] = v1;
    }
}

// ---------------- tiny attention over the expert axis (E=8) -----------------
// One block per token; one warp per head. q is the expert_id row only.
// scores[f] = q . k_f / sqrt(HD) + (f <= eid ? 1 : 0)   (additive float tril mask)
__global__ void attn_kernel(const float* __restrict__ q,
                            const float* __restrict__ kbuf,
                            const float* __restrict__ vbuf,
                            float* __restrict__ ctx,
                            const int* __restrict__ eidPtr)
{
    const int n    = blockIdx.x;
    const int head = threadIdx.x >> 5;
    const int lane = threadIdx.x & 31;
    const int eid  = *eidPtr;

    const int base = n * DD + head * HD;                  // + 2*lane for this lane's pair
    const float2 qv = *(const float2*)(q + base + 2 * lane);

    float s[NE];
    #pragma unroll
    for (int f = 0; f < NE; f++) {
        const float2 kv = *(const float2*)(kbuf + (size_t)f * NTOK * DD + base + 2 * lane);
        float p = qv.x * kv.x + qv.y * kv.y;
        #pragma unroll
        for (int off = 16; off > 0; off >>= 1)
            p += __shfl_xor_sync(0xffffffffu, p, off);
        s[f] = p * 0.125f + ((f <= eid) ? 1.0f : 0.0f);   // 1/sqrt(64) = 0.125
    }

    float mx = s[0];
    #pragma unroll
    for (int f = 1; f < NE; f++) mx = fmaxf(mx, s[f]);
    float sum = 0.f;
    #pragma unroll
    for (int f = 0; f < NE; f++) { s[f] = expf(s[f] - mx); sum += s[f]; }
    const float inv = 1.f / sum;

    float cx = 0.f, cy = 0.f;
    #pragma unroll
    for (int f = 0; f < NE; f++) {
        const float2 vv = *(const float2*)(vbuf + (size_t)f * NTOK * DD + base + 2 * lane);
        const float p = s[f] * inv;
        cx += p * vv.x; cy += p * vv.y;
    }
    float2 out = { cx, cy };
    *(float2*)(ctx + base + 2 * lane) = out;
}

// -----------------------------------------------------------------------------
extern "C" void kernel_launch(void* const* d_in, const int* in_sizes, int n_in,
                              void* d_out, int out_size)
{
    const float* x  = (const float*)d_in[0];
    const float* W1 = (const float*)d_in[1];
    const float* b1 = (const float*)d_in[2];
    const float* W2 = (const float*)d_in[3];
    const float* b2 = (const float*)d_in[4];
    const float* Wq = (const float*)d_in[5];
    const float* bq = (const float*)d_in[6];
    const float* Wk = (const float*)d_in[7];
    const float* bk = (const float*)d_in[8];
    const float* Wv = (const float*)d_in[9];
    const float* bv = (const float*)d_in[10];
    const float* Wo = (const float*)d_in[11];
    const float* bo = (const float*)d_in[12];
    const int*  eid = (const int*)  d_in[13];

    float *hidden, *eo, *kb, *vb, *qb, *cb;
    cudaGetSymbolAddress((void**)&hidden, g_hidden);
    cudaGetSymbolAddress((void**)&eo,     g_eo);
    cudaGetSymbolAddress((void**)&kb,     g_k);
    cudaGetSymbolAddress((void**)&vb,     g_v);
    cudaGetSymbolAddress((void**)&qb,     g_q);
    cudaGetSymbolAddress((void**)&cb,     g_ctx);

    const int M = NTOK;
    dim3 blk(256);

    // FFN1: hidden[e] = relu(x @ W1[e] + b1[e])   [4096,512]x[512,2048]
    {
        dim3 grid(DFF / 128, M / 128, NE);
        sgemm_kernel<false, true><<<grid, blk>>>(
            x, W1, b1, hidden, M, DFF, DD,
            0, (size_t)DD * DFF, DFF, (size_t)M * DFF, nullptr, 0);
    }
    // FFN2: eo[e] = hidden[e] @ W2[e] + b2[e]     [4096,2048]x[2048,512]
    {
        dim3 grid(DD / 128, M / 128, NE);
        sgemm_kernel<false, false><<<grid, blk>>>(
            hidden, W2, b2, eo, M, DD, DFF,
            (size_t)M * DFF, (size_t)DFF * DD, DD, (size_t)M * DD, nullptr, 0);
    }
    // K proj: k[e] = eo[e] @ Wk^T + bk
    {
        dim3 grid(DD / 128, M / 128, NE);
        sgemm_kernel<true, false><<<grid, blk>>>(
            eo, Wk, bk, kb, M, DD, DD,
            (size_t)M * DD, 0, 0, (size_t)M * DD, nullptr, 0);
    }
    // V proj
    {
        dim3 grid(DD / 128, M / 128, NE);
        sgemm_kernel<true, false><<<grid, blk>>>(
            eo, Wv, bv, vb, M, DD, DD,
            (size_t)M * DD, 0, 0, (size_t)M * DD, nullptr, 0);
    }
    // Q proj — only the expert_id row of eo (offset resolved on device)
    {
        dim3 grid(DD / 128, M / 128, 1);
        sgemm_kernel<true, false><<<grid, blk>>>(
            eo, Wq, bq, qb, M, DD, DD,
            0, 0, 0, 0, eid, (size_t)M * DD);
    }
    // attention over experts (row = expert_id only)
    attn_kernel<<<M, 256>>>(qb, kb, vb, cb, eid);

    // out proj: out = ctx @ Wo^T + bo  -> d_out [4096, 512]
    {
        dim3 grid(DD / 128, M / 128, 1);
        sgemm_kernel<true, false><<<grid, blk>>>(
            cb, Wo, bo, (float*)d_out, M, DD, DD,
            0, 0, 0, 0, nullptr, 0);
    }
}

// round 3
// speedup vs baseline: 1.8508x; 1.8508x over previous
#include <cuda_runtime.h>
#include <cuda_bf16.h>

typedef unsigned int u32;
typedef unsigned long long u64;

#define NE   8
#define DD   512
#define DFF  2048
#define NTOK 4096

// ---------------- device scratch (no allocation allowed) ----------------
__device__ __nv_bfloat16 g_xh[(size_t)NTOK*DD],      g_xl[(size_t)NTOK*DD];
__device__ __nv_bfloat16 g_w1h[(size_t)NE*DFF*DD],   g_w1l[(size_t)NE*DFF*DD];   // W1^T per expert [2048,512]
__device__ __nv_bfloat16 g_w2h[(size_t)NE*DD*DFF],   g_w2l[(size_t)NE*DD*DFF];   // W2^T per expert [512,2048]
__device__ __nv_bfloat16 g_wqh[DD*DD], g_wql[DD*DD], g_wkh[DD*DD], g_wkl[DD*DD];
__device__ __nv_bfloat16 g_wvh[DD*DD], g_wvl[DD*DD], g_woh[DD*DD], g_wol[DD*DD];
__device__ __nv_bfloat16 g_hidh[(size_t)NE*NTOK*DFF], g_hidl[(size_t)NE*NTOK*DFF];
__device__ __nv_bfloat16 g_eoh[(size_t)NE*NTOK*DD],   g_eol[(size_t)NE*NTOK*DD];
__device__ float g_k[(size_t)NE*NTOK*DD];
__device__ float g_v[(size_t)NE*NTOK*DD];
__device__ float g_q[(size_t)NTOK*DD];
__device__ __nv_bfloat16 g_cxh[(size_t)NTOK*DD], g_cxl[(size_t)NTOK*DD];

// ---------------- helpers ----------------
__device__ __forceinline__ u32 smem_u32(const void* p) {
    return (u32)__cvta_generic_to_shared(p);
}
__device__ __forceinline__ void cpa16(u32 dst, const void* src) {
    asm volatile("cp.async.cg.shared.global [%0], [%1], 16;" :: "r"(dst), "l"(src));
}
#define CPA_COMMIT() asm volatile("cp.async.commit_group;" ::: "memory")
#define CPA_WAIT2()  asm volatile("cp.async.wait_group 2;" ::: "memory")

__device__ __forceinline__ void ldsm_x4(u32* r, u32 addr) {
    asm volatile("ldmatrix.sync.aligned.m8n8.x4.shared.b16 {%0,%1,%2,%3}, [%4];"
                 : "=r"(r[0]), "=r"(r[1]), "=r"(r[2]), "=r"(r[3]) : "r"(addr));
}
__device__ __forceinline__ void ldsm_x2(u32* r, u32 addr) {
    asm volatile("ldmatrix.sync.aligned.m8n8.x2.shared.b16 {%0,%1}, [%2];"
                 : "=r"(r[0]), "=r"(r[1]) : "r"(addr));
}
__device__ __forceinline__ void mma16816(float* c, const u32* a, const u32* b) {
    asm volatile(
        "mma.sync.aligned.m16n8k16.row.col.f32.bf16.bf16.f32 "
        "{%0,%1,%2,%3}, {%4,%5,%6,%7}, {%8,%9}, {%0,%1,%2,%3};"
        : "+f"(c[0]), "+f"(c[1]), "+f"(c[2]), "+f"(c[3])
        : "r"(a[0]), "r"(a[1]), "r"(a[2]), "r"(a[3]), "r"(b[0]), "r"(b[1]));
}
__device__ __forceinline__ void split2(float v, __nv_bfloat16& h, __nv_bfloat16& l) {
    h = __float2bfloat16(v);
    l = __float2bfloat16(v - __bfloat162float(h));
}

// smem geometry: 4 slabs (Ah, Al, Bh, Bl), each 128 rows x 80 bytes (32 bf16 + pad)
#define KTILE   32
#define ROWB    80
#define SLAB    (128 * ROWB)       // 10240
#define STAGEB  (4 * SLAB)         // 40960
#define NSTAGE  3
#define SMEM_BYTES (NSTAGE * STAGEB)

// ---------------- bf16x3 mma.sync GEMM ----------------
// D[m,n] = sum_k A[m,k]*B[n,k] + bias[n]; A,B split bf16 (hi,lo), K-major rows.
// Block 128x128xK, k-tile 32, 8 warps (2x4), warp tile 64x32.
// OUTMODE: 0 -> fp32 Cf ; 1 -> split bf16 Chi/Clo.
template<int OUTMODE, bool RELU>
__global__ void __launch_bounds__(256, 1) mma_gemm(
    const __nv_bfloat16* __restrict__ Ahi, const __nv_bfloat16* __restrict__ Alo,
    const __nv_bfloat16* __restrict__ Bhi, const __nv_bfloat16* __restrict__ Blo,
    const float* __restrict__ biasg,
    float* __restrict__ Cf,
    __nv_bfloat16* __restrict__ Chi, __nv_bfloat16* __restrict__ Clo,
    int N, int K,
    size_t sA, size_t sB, size_t sBias, size_t sC,
    const int* __restrict__ eidPtr, size_t eidStride)
{
    extern __shared__ __align__(128) char sm[];
    const int tid  = threadIdx.x;
    const int lane = tid & 31;
    const int wid  = tid >> 5;
    const int e    = blockIdx.z;
    const int m0   = blockIdx.y * 128;
    const int n0   = blockIdx.x * 128;

    size_t aoff = (size_t)e * sA;
    if (eidPtr) aoff += (size_t)(*eidPtr) * eidStride;
    const __nv_bfloat16* pAh = Ahi + aoff;
    const __nv_bfloat16* pAl = Alo + aoff;
    const __nv_bfloat16* pBh = Bhi + (size_t)e * sB;
    const __nv_bfloat16* pBl = Blo + (size_t)e * sB;
    const float* bias = biasg + (size_t)e * sBias;

    const u32 smb = smem_u32(sm);

    // ---- loader mapping: thread covers row lr, 16B chunks lc, lc+1 ----
    const int lr = tid >> 1;
    const int lc = (tid & 1) * 2;
    const __nv_bfloat16* gAh = pAh + (size_t)(m0 + lr) * K + lc * 8;
    const __nv_bfloat16* gAl = pAl + (size_t)(m0 + lr) * K + lc * 8;
    const __nv_bfloat16* gBh = pBh + (size_t)(n0 + lr) * K + lc * 8;
    const __nv_bfloat16* gBl = pBl + (size_t)(n0 + lr) * K + lc * 8;
    const u32 so = (u32)(lr * ROWB + lc * 16);

    // ---- warp/compute mapping ----
    const int wm = wid >> 2;       // 0..1 -> m offset 0/64
    const int wn = wid & 3;        // 0..3 -> n offset 0/32/64/96

    // ldmatrix lane offsets (byte offsets within slab)
    u32 offA[4][2], offB[4][2];
    {
        const int rA = wm * 64 + (lane & 15);
        const int cA = (lane >> 4);            // 0/1
        #pragma unroll
        for (int im = 0; im < 4; im++)
            #pragma unroll
            for (int ks = 0; ks < 2; ks++)
                offA[im][ks] = (u32)((rA + im * 16) * ROWB + (ks * 2 + cA) * 16);
        const int rB = wn * 32 + (lane & 7);
        const int cB = (lane >> 3) & 1;        // 0/1 (lanes>=16 replicate, ignored by x2)
        #pragma unroll
        for (int in = 0; in < 4; in++)
            #pragma unroll
            for (int ks = 0; ks < 2; ks++)
                offB[in][ks] = (u32)((rB + in * 8) * ROWB + (ks * 2 + cB) * 16);
    }

    float acc[4][4][4];
    #pragma unroll
    for (int im = 0; im < 4; im++)
        #pragma unroll
        for (int in = 0; in < 4; in++)
            #pragma unroll
            for (int q = 0; q < 4; q++) acc[im][in][q] = 0.f;

    const int nt = K >> 5;

    // ---- prologue: fill 3 stages ----
    #pragma unroll
    for (int p = 0; p < NSTAGE; p++) {
        const int k0 = p * KTILE;
        const u32 b = smb + p * STAGEB + so;
        cpa16(b,                 gAh + k0); cpa16(b + 16,            gAh + k0 + 8);
        cpa16(b + SLAB,          gAl + k0); cpa16(b + SLAB + 16,     gAl + k0 + 8);
        cpa16(b + 2 * SLAB,      gBh + k0); cpa16(b + 2 * SLAB + 16, gBh + k0 + 8);
        cpa16(b + 3 * SLAB,      gBl + k0); cpa16(b + 3 * SLAB + 16, gBl + k0 + 8);
        CPA_COMMIT();
    }

    for (int i = 0; i < nt; i++) {
        CPA_WAIT2();
        __syncthreads();

        const u32 stage = smb + (u32)(i % NSTAGE) * STAGEB;
        #pragma unroll
        for (int ks = 0; ks < 2; ks++) {
            u32 ah[4][4], al[4][4];
            #pragma unroll
            for (int im = 0; im < 4; im++) {
                ldsm_x4(ah[im], stage + offA[im][ks]);
                ldsm_x4(al[im], stage + SLAB + offA[im][ks]);
            }
            u32 bh[4][2], bl[4][2];
            #pragma unroll
            for (int in = 0; in < 4; in++) {
                ldsm_x2(bh[in], stage + 2 * SLAB + offB[in][ks]);
                ldsm_x2(bl[in], stage + 3 * SLAB + offB[in][ks]);
            }
            #pragma unroll
            for (int im = 0; im < 4; im++)
                #pragma unroll
                for (int in = 0; in < 4; in++) {
                    mma16816(acc[im][in], ah[im], bh[in]);
                    mma16816(acc[im][in], ah[im], bl[in]);
                    mma16816(acc[im][in], al[im], bh[in]);
                }
        }
        __syncthreads();

        const int inext = i + NSTAGE;
        if (inext < nt) {
            const int k0 = inext * KTILE;
            const u32 b = smb + (u32)(i % NSTAGE) * STAGEB + so;
            cpa16(b,                 gAh + k0); cpa16(b + 16,            gAh + k0 + 8);
            cpa16(b + SLAB,          gAl + k0); cpa16(b + SLAB + 16,     gAl + k0 + 8);
            cpa16(b + 2 * SLAB,      gBh + k0); cpa16(b + 2 * SLAB + 16, gBh + k0 + 8);
            cpa16(b + 3 * SLAB,      gBl + k0); cpa16(b + 3 * SLAB + 16, gBl + k0 + 8);
        }
        CPA_COMMIT();   // commit every iter to keep group accounting uniform
    }

    // ---- epilogue ----
    const int g = lane >> 2;
    const int cb_in = (lane & 3) * 2;
    #pragma unroll
    for (int in = 0; in < 4; in++) {
        const int col = n0 + wn * 32 + in * 8 + cb_in;
        const float bx = bias[col], by = bias[col + 1];
        #pragma unroll
        for (int im = 0; im < 4; im++) {
            const int r0 = m0 + wm * 64 + im * 16 + g;
            const int r1 = r0 + 8;
            float v00 = acc[im][in][0] + bx, v01 = acc[im][in][1] + by;
            float v10 = acc[im][in][2] + bx, v11 = acc[im][in][3] + by;
            if (RELU) {
                v00 = fmaxf(v00, 0.f); v01 = fmaxf(v01, 0.f);
                v10 = fmaxf(v10, 0.f); v11 = fmaxf(v11, 0.f);
            }
            if (OUTMODE == 0) {
                float* o = Cf + (size_t)e * sC;
                float2 a0 = {v00, v01}, a1 = {v10, v11};
                *(float2*)(o + (size_t)r0 * N + col) = a0;
                *(float2*)(o + (size_t)r1 * N + col) = a1;
            } else {
                __nv_bfloat16 h00, l00, h01, l01, h10, l10, h11, l11;
                split2(v00, h00, l00); split2(v01, h01, l01);
                split2(v10, h10, l10); split2(v11, h11, l11);
                __nv_bfloat16* oh = Chi + (size_t)e * sC;
                __nv_bfloat16* ol = Clo + (size_t)e * sC;
                __nv_bfloat162 p;
                p.x = h00; p.y = h01; *(__nv_bfloat162*)(oh + (size_t)r0 * N + col) = p;
                p.x = l00; p.y = l01; *(__nv_bfloat162*)(ol + (size_t)r0 * N + col) = p;
                p.x = h10; p.y = h11; *(__nv_bfloat162*)(oh + (size_t)r1 * N + col) = p;
                p.x = l10; p.y = l11; *(__nv_bfloat162*)(ol + (size_t)r1 * N + col) = p;
            }
        }
    }
}

// ---------------- conversion kernels ----------------
__global__ void k_split(const float* __restrict__ in,
                        __nv_bfloat16* __restrict__ hi, __nv_bfloat16* __restrict__ lo,
                        int n4)
{
    const int i = blockIdx.x * 256 + threadIdx.x;
    if (i >= n4) return;
    const float4 u = ((const float4*)in)[i];
    __nv_bfloat16 h[4], l[4];
    split2(u.x, h[0], l[0]); split2(u.y, h[1], l[1]);
    split2(u.z, h[2], l[2]); split2(u.w, h[3], l[3]);
    ((uint2*)hi)[i] = *(const uint2*)h;
    ((uint2*)lo)[i] = *(const uint2*)l;
}

// transpose + split: in [R,C] fp32 (batched over z) -> out [C,R] bf16 hi/lo
__global__ void k_tsplit(const float* __restrict__ in,
                         __nv_bfloat16* __restrict__ hi, __nv_bfloat16* __restrict__ lo,
                         int R, int C)
{
    __shared__ float t[32][33];
    const size_t zo = (size_t)blockIdx.z * R * C;
    const int c0 = blockIdx.x * 32, r0 = blockIdx.y * 32;
    const int tx = threadIdx.x, ty = threadIdx.y;
    #pragma unroll
    for (int rr = ty; rr < 32; rr += 8)
        t[rr][tx] = in[zo + (size_t)(r0 + rr) * C + c0 + tx];
    __syncthreads();
    #pragma unroll
    for (int cc = ty; cc < 32; cc += 8) {
        __nv_bfloat16 h, l;
        split2(t[tx][cc], h, l);
        const size_t o = zo + (size_t)(c0 + cc) * R + r0 + tx;
        hi[o] = h; lo[o] = l;
    }
}

// ---------------- attention over the expert axis (E=8) ----------------
__global__ void attn_kernel(const float* __restrict__ q,
                            const float* __restrict__ kbuf,
                            const float* __restrict__ vbuf,
                            __nv_bfloat16* __restrict__ ctxh,
                            __nv_bfloat16* __restrict__ ctxl,
                            const int* __restrict__ eidPtr)
{
    const int n    = blockIdx.x;
    const int head = threadIdx.x >> 5;
    const int lane = threadIdx.x & 31;
    const int eid  = *eidPtr;

    const int base = n * DD + head * 64 + 2 * lane;
    const float2 qv = *(const float2*)(q + base);

    float s[NE];
    #pragma unroll
    for (int f = 0; f < NE; f++) {
        const float2 kv = *(const float2*)(kbuf + (size_t)f * NTOK * DD + base);
        float p = qv.x * kv.x + qv.y * kv.y;
        #pragma unroll
        for (int off = 16; off > 0; off >>= 1)
            p += __shfl_xor_sync(0xffffffffu, p, off);
        s[f] = p * 0.125f + ((f <= eid) ? 1.0f : 0.0f);
    }

    float mx = s[0];
    #pragma unroll
    for (int f = 1; f < NE; f++) mx = fmaxf(mx, s[f]);
    float sum = 0.f;
    #pragma unroll
    for (int f = 0; f < NE; f++) { s[f] = expf(s[f] - mx); sum += s[f]; }
    const float inv = 1.f / sum;

    float cx = 0.f, cy = 0.f;
    #pragma unroll
    for (int f = 0; f < NE; f++) {
        const float2 vv = *(const float2*)(vbuf + (size_t)f * NTOK * DD + base);
        const float p = s[f] * inv;
        cx += p * vv.x; cy += p * vv.y;
    }
    __nv_bfloat16 hx, lx, hy, ly;
    split2(cx, hx, lx); split2(cy, hy, ly);
    __nv_bfloat162 hh; hh.x = hx; hh.y = hy;
    __nv_bfloat162 ll; ll.x = lx; ll.y = ly;
    *(__nv_bfloat162*)(ctxh + base) = hh;
    *(__nv_bfloat162*)(ctxl + base) = ll;
}

// -----------------------------------------------------------------------------
extern "C" void kernel_launch(void* const* d_in, const int* in_sizes, int n_in,
                              void* d_out, int out_size)
{
    const float* x  = (const float*)d_in[0];
    const float* W1 = (const float*)d_in[1];
    const float* b1 = (const float*)d_in[2];
    const float* W2 = (const float*)d_in[3];
    const float* b2 = (const float*)d_in[4];
    const float* Wq = (const float*)d_in[5];
    const float* bq = (const float*)d_in[6];
    const float* Wk = (const float*)d_in[7];
    const float* bk = (const float*)d_in[8];
    const float* Wv = (const float*)d_in[9];
    const float* bv = (const float*)d_in[10];
    const float* Wo = (const float*)d_in[11];
    const float* bo = (const float*)d_in[12];
    const int*  eid = (const int*)  d_in[13];

    __nv_bfloat16 *xh, *xl, *w1h, *w1l, *w2h, *w2l;
    __nv_bfloat16 *wqh, *wql, *wkh, *wkl, *wvh, *wvl, *woh, *wol;
    __nv_bfloat16 *hidh, *hidl, *eoh, *eol, *cxh, *cxl;
    float *kb, *vb, *qb;
    cudaGetSymbolAddress((void**)&xh,  g_xh);  cudaGetSymbolAddress((void**)&xl,  g_xl);
    cudaGetSymbolAddress((void**)&w1h, g_w1h); cudaGetSymbolAddress((void**)&w1l, g_w1l);
    cudaGetSymbolAddress((void**)&w2h, g_w2h); cudaGetSymbolAddress((void**)&w2l, g_w2l);
    cudaGetSymbolAddress((void**)&wqh, g_wqh); cudaGetSymbolAddress((void**)&wql, g_wql);
    cudaGetSymbolAddress((void**)&wkh, g_wkh); cudaGetSymbolAddress((void**)&wkl, g_wkl);
    cudaGetSymbolAddress((void**)&wvh, g_wvh); cudaGetSymbolAddress((void**)&wvl, g_wvl);
    cudaGetSymbolAddress((void**)&woh, g_woh); cudaGetSymbolAddress((void**)&wol, g_wol);
    cudaGetSymbolAddress((void**)&hidh, g_hidh); cudaGetSymbolAddress((void**)&hidl, g_hidl);
    cudaGetSymbolAddress((void**)&eoh, g_eoh); cudaGetSymbolAddress((void**)&eol, g_eol);
    cudaGetSymbolAddress((void**)&cxh, g_cxh); cudaGetSymbolAddress((void**)&cxl, g_cxl);
    cudaGetSymbolAddress((void**)&kb,  g_k);   cudaGetSymbolAddress((void**)&vb,  g_v);
    cudaGetSymbolAddress((void**)&qb,  g_q);

    cudaFuncSetAttribute(mma_gemm<0, false>, cudaFuncAttributeMaxDynamicSharedMemorySize, SMEM_BYTES);
    cudaFuncSetAttribute(mma_gemm<1, false>, cudaFuncAttributeMaxDynamicSharedMemorySize, SMEM_BYTES);
    cudaFuncSetAttribute(mma_gemm<1, true>,  cudaFuncAttributeMaxDynamicSharedMemorySize, SMEM_BYTES);

    // ---- conversions ----
    k_split<<<(NTOK * DD / 4 + 255) / 256, 256>>>(x, xh, xl, NTOK * DD / 4);
    k_split<<<(DD * DD / 4 + 255) / 256, 256>>>(Wq, wqh, wql, DD * DD / 4);
    k_split<<<(DD * DD / 4 + 255) / 256, 256>>>(Wk, wkh, wkl, DD * DD / 4);
    k_split<<<(DD * DD / 4 + 255) / 256, 256>>>(Wv, wvh, wvl, DD * DD / 4);
    k_split<<<(DD * DD / 4 + 255) / 256, 256>>>(Wo, woh, wol, DD * DD / 4);
    {   // W1 [E,512,2048] -> [E,2048,512]
        dim3 g(DFF / 32, DD / 32, NE), b(32, 8);
        k_tsplit<<<g, b>>>(W1, w1h, w1l, DD, DFF);
    }
    {   // W2 [E,2048,512] -> [E,512,2048]
        dim3 g(DD / 32, DFF / 32, NE), b(32, 8);
        k_tsplit<<<g, b>>>(W2, w2h, w2l, DFF, DD);
    }

    // ---- FFN1: hidden[e] = relu(x @ W1[e] + b1[e])  [4096,2048] K=512 ----
    mma_gemm<1, true><<<dim3(DFF / 128, NTOK / 128, NE), 256, SMEM_BYTES>>>(
        xh, xl, w1h, w1l, b1, nullptr, hidh, hidl,
        DFF, DD, 0, (size_t)DFF * DD, DFF, (size_t)NTOK * DFF, nullptr, 0);

    // ---- FFN2: eo[e] = hidden[e] @ W2[e] + b2[e]  [4096,512] K=2048 ----
    mma_gemm<1, false><<<dim3(DD / 128, NTOK / 128, NE), 256, SMEM_BYTES>>>(
        hidh, hidl, w2h, w2l, b2, nullptr, eoh, eol,
        DD, DFF, (size_t)NTOK * DFF, (size_t)DD * DFF, DD, (size_t)NTOK * DD, nullptr, 0);

    // ---- K proj: k[e] = eo[e] @ Wk^T + bk ----
    mma_gemm<0, false><<<dim3(DD / 128, NTOK / 128, NE), 256, SMEM_BYTES>>>(
        eoh, eol, wkh, wkl, bk, kb, nullptr, nullptr,
        DD, DD, (size_t)NTOK * DD, 0, 0, (size_t)NTOK * DD, nullptr, 0);

    // ---- V proj ----
    mma_gemm<0, false><<<dim3(DD / 128, NTOK / 128, NE), 256, SMEM_BYTES>>>(
        eoh, eol, wvh, wvl, bv, vb, nullptr, nullptr,
        DD, DD, (size_t)NTOK * DD, 0, 0, (size_t)NTOK * DD, nullptr, 0);

    // ---- Q proj (expert_id slice only) ----
    mma_gemm<0, false><<<dim3(DD / 128, NTOK / 128, 1), 256, SMEM_BYTES>>>(
        eoh, eol, wqh, wql, bq, qb, nullptr, nullptr,
        DD, DD, 0, 0, 0, 0, eid, (size_t)NTOK * DD);

    // ---- attention over experts ----
    attn_kernel<<<NTOK, 256>>>(qb, kb, vb, cxh, cxl, eid);

    // ---- out proj: d_out = ctx @ Wo^T + bo ----
    mma_gemm<0, false><<<dim3(DD / 128, NTOK / 128, 1), 256, SMEM_BYTES>>>(
        cxh, cxl, woh, wol, bo, (float*)d_out, nullptr, nullptr,
        DD, DD, 0, 0, 0, 0, nullptr, 0);
}

// round 4
// speedup vs baseline: 1.9798x; 1.0697x over previous
#include <cuda_runtime.h>
#include <cuda_bf16.h>

typedef unsigned int u32;
typedef unsigned long long u64;

#define NE   8
#define DD   512
#define DFF  2048
#define NTOK 4096

// ---------------- device scratch (no allocation allowed) ----------------
__device__ __nv_bfloat16 g_xh[(size_t)NTOK*DD],      g_xl[(size_t)NTOK*DD];
__device__ __nv_bfloat16 g_w1h[(size_t)NE*DFF*DD],   g_w1l[(size_t)NE*DFF*DD];   // W1^T per expert [2048,512]
__device__ __nv_bfloat16 g_w2h[(size_t)NE*DD*DFF],   g_w2l[(size_t)NE*DD*DFF];   // W2^T per expert [512,2048]
__device__ __nv_bfloat16 g_wqh[DD*DD], g_wql[DD*DD];
__device__ __nv_bfloat16 g_wkvh[2*DD*DD], g_wkvl[2*DD*DD];   // [Wk;Wv] rows concat -> [1024,512]
__device__ __nv_bfloat16 g_woh[DD*DD], g_wol[DD*DD];
__device__ float g_bkv[2*DD];
__device__ __nv_bfloat16 g_hidh[(size_t)NE*NTOK*DFF], g_hidl[(size_t)NE*NTOK*DFF];
__device__ __nv_bfloat16 g_eoh[(size_t)NE*NTOK*DD],   g_eol[(size_t)NE*NTOK*DD];
__device__ float g_kv[(size_t)NE*NTOK*2*DD];   // [e][tok][0:512]=k, [512:1024]=v
__device__ float g_q[(size_t)NTOK*DD];
__device__ __nv_bfloat16 g_cxh[(size_t)NTOK*DD], g_cxl[(size_t)NTOK*DD];

// ---------------- helpers ----------------
__device__ __forceinline__ u32 smem_u32(const void* p) {
    return (u32)__cvta_generic_to_shared(p);
}
__device__ __forceinline__ void cpa16(u32 dst, const void* src) {
    asm volatile("cp.async.cg.shared.global [%0], [%1], 16;" :: "r"(dst), "l"(src));
}
#define CPA_COMMIT() asm volatile("cp.async.commit_group;" ::: "memory")
#define CPA_WAIT1()  asm volatile("cp.async.wait_group 1;" ::: "memory")

__device__ __forceinline__ void ldsm_x4(u32* r, u32 addr) {
    asm volatile("ldmatrix.sync.aligned.m8n8.x4.shared.b16 {%0,%1,%2,%3}, [%4];"
                 : "=r"(r[0]), "=r"(r[1]), "=r"(r[2]), "=r"(r[3]) : "r"(addr));
}
__device__ __forceinline__ void ldsm_x2(u32* r, u32 addr) {
    asm volatile("ldmatrix.sync.aligned.m8n8.x2.shared.b16 {%0,%1}, [%2];"
                 : "=r"(r[0]), "=r"(r[1]) : "r"(addr));
}
__device__ __forceinline__ void mma16816(float* c, const u32* a, const u32* b) {
    asm volatile(
        "mma.sync.aligned.m16n8k16.row.col.f32.bf16.bf16.f32 "
        "{%0,%1,%2,%3}, {%4,%5,%6,%7}, {%8,%9}, {%0,%1,%2,%3};"
        : "+f"(c[0]), "+f"(c[1]), "+f"(c[2]), "+f"(c[3])
        : "r"(a[0]), "r"(a[1]), "r"(a[2]), "r"(a[3]), "r"(b[0]), "r"(b[1]));
}
__device__ __forceinline__ void split2(float v, __nv_bfloat16& h, __nv_bfloat16& l) {
    h = __float2bfloat16(v);
    l = __float2bfloat16(v - __bfloat162float(h));
}

// smem geometry: tile 64x128, ktile 32 (64B/row + 16 pad = 80B rows)
#define KTILE   32
#define ROWB    80
#define OFF_AH  0
#define OFF_AL  (64*ROWB)          // 5120
#define OFF_BH  (128*ROWB)         // 10240
#define OFF_BL  (OFF_BH + 128*ROWB)// 20480
#define STAGEB  (OFF_BL + 128*ROWB)// 30720
#define NSTAGE  3
#define SMEM_BYTES (NSTAGE * STAGEB)   // 92160

// ---------------- bf16x3 mma.sync GEMM ----------------
// D[m,n] = sum_k A[m,k]*B[n,k] + bias[n]; A,B split bf16 (hi,lo), K-major rows.
// Block tile 64x128, 8 warps (2x4), warp tile 32x32, 3-stage cp.async pipeline,
// one __syncthreads per k-tile, 2 CTAs/SM.
template<int OUTMODE, bool RELU>
__global__ void __launch_bounds__(256, 2) mma_gemm(
    const __nv_bfloat16* __restrict__ Ahi, const __nv_bfloat16* __restrict__ Alo,
    const __nv_bfloat16* __restrict__ Bhi, const __nv_bfloat16* __restrict__ Blo,
    const float* __restrict__ biasg,
    float* __restrict__ Cf,
    __nv_bfloat16* __restrict__ Chi, __nv_bfloat16* __restrict__ Clo,
    int N, int K,
    size_t sA, size_t sB, size_t sBias, size_t sC,
    const int* __restrict__ eidPtr, size_t eidStride)
{
    extern __shared__ __align__(128) char sm[];
    const int tid  = threadIdx.x;
    const int lane = tid & 31;
    const int wid  = tid >> 5;
    const int e    = blockIdx.z;
    const int m0   = blockIdx.y * 64;
    const int n0   = blockIdx.x * 128;

    size_t aoff = (size_t)e * sA;
    if (eidPtr) aoff += (size_t)(*eidPtr) * eidStride;
    const __nv_bfloat16* pAh = Ahi + aoff;
    const __nv_bfloat16* pAl = Alo + aoff;
    const __nv_bfloat16* pBh = Bhi + (size_t)e * sB;
    const __nv_bfloat16* pBl = Blo + (size_t)e * sB;
    const float* bias = biasg + (size_t)e * sBias;

    const u32 smb = smem_u32(sm);

    // ---- loader mapping ----
    const int lrA = tid >> 2, lcA = tid & 3;            // A: 64 rows x 4 chunks
    const int lrB = tid >> 1, lcB = (tid & 1) * 2;      // B: 128 rows x 2x2 chunks
    const __nv_bfloat16* gAh = pAh + (size_t)(m0 + lrA) * K + lcA * 8;
    const __nv_bfloat16* gAl = pAl + (size_t)(m0 + lrA) * K + lcA * 8;
    const __nv_bfloat16* gBh = pBh + (size_t)(n0 + lrB) * K + lcB * 8;
    const __nv_bfloat16* gBl = pBl + (size_t)(n0 + lrB) * K + lcB * 8;
    const u32 soA = (u32)(lrA * ROWB + lcA * 16);
    const u32 soB = (u32)(lrB * ROWB + lcB * 16);

    // ---- warp/compute mapping: warps 2x4, warp tile 32x32 ----
    const int wm = wid >> 2;       // 0..1 -> m offset 0/32
    const int wn = wid & 3;        // 0..3 -> n offset 0/32/64/96

    u32 offA[2][2], offB[4][2];
    {
        const int rA = wm * 32 + (lane & 15);
        const int cA = lane >> 4;
        #pragma unroll
        for (int im = 0; im < 2; im++)
            #pragma unroll
            for (int ks = 0; ks < 2; ks++)
                offA[im][ks] = (u32)((rA + im * 16) * ROWB + (ks * 2 + cA) * 16);
        const int rB = wn * 32 + (lane & 7);
        const int cB = (lane >> 3) & 1;
        #pragma unroll
        for (int in = 0; in < 4; in++)
            #pragma unroll
            for (int ks = 0; ks < 2; ks++)
                offB[in][ks] = (u32)((rB + in * 8) * ROWB + (ks * 2 + cB) * 16);
    }

    float acc[2][4][4];
    #pragma unroll
    for (int im = 0; im < 2; im++)
        #pragma unroll
        for (int in = 0; in < 4; in++)
            #pragma unroll
            for (int q = 0; q < 4; q++) acc[im][in][q] = 0.f;

    const int nt = K >> 5;

    // ---- prologue: stages 0,1 ----
    #pragma unroll
    for (int p = 0; p < 2; p++) {
        const int k0 = p * KTILE;
        const u32 b = smb + p * STAGEB;
        cpa16(b + OFF_AH + soA, gAh + k0);
        cpa16(b + OFF_AL + soA, gAl + k0);
        cpa16(b + OFF_BH + soB,      gBh + k0);
        cpa16(b + OFF_BH + soB + 16, gBh + k0 + 8);
        cpa16(b + OFF_BL + soB,      gBl + k0);
        cpa16(b + OFF_BL + soB + 16, gBl + k0 + 8);
        CPA_COMMIT();
    }

    int slot = 0;           // slot of stage i
    int wslot = 2;          // slot to write stage i+2
    for (int i = 0; i < nt; i++) {
        CPA_WAIT1();
        __syncthreads();

        // issue loads for tile i+2 into wslot (its readers finished before the barrier)
        const int inext = i + 2;
        if (inext < nt) {
            const int k0 = inext * KTILE;
            const u32 b = smb + (u32)wslot * STAGEB;
            cpa16(b + OFF_AH + soA, gAh + k0);
            cpa16(b + OFF_AL + soA, gAl + k0);
            cpa16(b + OFF_BH + soB,      gBh + k0);
            cpa16(b + OFF_BH + soB + 16, gBh + k0 + 8);
            cpa16(b + OFF_BL + soB,      gBl + k0);
            cpa16(b + OFF_BL + soB + 16, gBl + k0 + 8);
        }
        CPA_COMMIT();

        const u32 stage = smb + (u32)slot * STAGEB;
        #pragma unroll
        for (int ks = 0; ks < 2; ks++) {
            u32 ah[2][4], al[2][4];
            #pragma unroll
            for (int im = 0; im < 2; im++) {
                ldsm_x4(ah[im], stage + OFF_AH + offA[im][ks]);
                ldsm_x4(al[im], stage + OFF_AL + offA[im][ks]);
            }
            u32 bh[4][2], bl[4][2];
            #pragma unroll
            for (int in = 0; in < 4; in++) {
                ldsm_x2(bh[in], stage + OFF_BH + offB[in][ks]);
                ldsm_x2(bl[in], stage + OFF_BL + offB[in][ks]);
            }
            #pragma unroll
            for (int im = 0; im < 2; im++)
                #pragma unroll
                for (int in = 0; in < 4; in++) {
                    mma16816(acc[im][in], ah[im], bh[in]);
                    mma16816(acc[im][in], ah[im], bl[in]);
                    mma16816(acc[im][in], al[im], bh[in]);
                }
        }
        slot  = (slot  == 2) ? 0 : slot + 1;
        wslot = (wslot == 2) ? 0 : wslot + 1;
    }

    // ---- epilogue ----
    const int g = lane >> 2;
    const int cb_in = (lane & 3) * 2;
    #pragma unroll
    for (int in = 0; in < 4; in++) {
        const int col = n0 + wn * 32 + in * 8 + cb_in;
        const float bx = bias[col], by = bias[col + 1];
        #pragma unroll
        for (int im = 0; im < 2; im++) {
            const int r0 = m0 + wm * 32 + im * 16 + g;
            const int r1 = r0 + 8;
            float v00 = acc[im][in][0] + bx, v01 = acc[im][in][1] + by;
            float v10 = acc[im][in][2] + bx, v11 = acc[im][in][3] + by;
            if (RELU) {
                v00 = fmaxf(v00, 0.f); v01 = fmaxf(v01, 0.f);
                v10 = fmaxf(v10, 0.f); v11 = fmaxf(v11, 0.f);
            }
            if (OUTMODE == 0) {
                float* o = Cf + (size_t)e * sC;
                float2 a0 = {v00, v01}, a1 = {v10, v11};
                *(float2*)(o + (size_t)r0 * N + col) = a0;
                *(float2*)(o + (size_t)r1 * N + col) = a1;
            } else {
                __nv_bfloat16 h00, l00, h01, l01, h10, l10, h11, l11;
                split2(v00, h00, l00); split2(v01, h01, l01);
                split2(v10, h10, l10); split2(v11, h11, l11);
                __nv_bfloat16* oh = Chi + (size_t)e * sC;
                __nv_bfloat16* ol = Clo + (size_t)e * sC;
                __nv_bfloat162 p;
                p.x = h00; p.y = h01; *(__nv_bfloat162*)(oh + (size_t)r0 * N + col) = p;
                p.x = l00; p.y = l01; *(__nv_bfloat162*)(ol + (size_t)r0 * N + col) = p;
                p.x = h10; p.y = h11; *(__nv_bfloat162*)(oh + (size_t)r1 * N + col) = p;
                p.x = l10; p.y = l11; *(__nv_bfloat162*)(ol + (size_t)r1 * N + col) = p;
            }
        }
    }
}

// ---------------- conversion kernels ----------------
__global__ void k_split(const float* __restrict__ in,
                        __nv_bfloat16* __restrict__ hi, __nv_bfloat16* __restrict__ lo,
                        int n4)
{
    const int i = blockIdx.x * 256 + threadIdx.x;
    if (i >= n4) return;
    const float4 u = ((const float4*)in)[i];
    __nv_bfloat16 h[4], l[4];
    split2(u.x, h[0], l[0]); split2(u.y, h[1], l[1]);
    split2(u.z, h[2], l[2]); split2(u.w, h[3], l[3]);
    ((uint2*)hi)[i] = *(const uint2*)h;
    ((uint2*)lo)[i] = *(const uint2*)l;
}

__global__ void k_cat_bias(const float* __restrict__ a, const float* __restrict__ b,
                           float* __restrict__ o)
{
    const int i = threadIdx.x + blockIdx.x * 256;
    if (i < DD) o[i] = a[i];
    else if (i < 2 * DD) o[i] = b[i - DD];
}

// transpose + split: in [R,C] fp32 (batched over z) -> out [C,R] bf16 hi/lo
__global__ void k_tsplit(const float* __restrict__ in,
                         __nv_bfloat16* __restrict__ hi, __nv_bfloat16* __restrict__ lo,
                         int R, int C)
{
    __shared__ float t[32][33];
    const size_t zo = (size_t)blockIdx.z * R * C;
    const int c0 = blockIdx.x * 32, r0 = blockIdx.y * 32;
    const int tx = threadIdx.x, ty = threadIdx.y;
    #pragma unroll
    for (int rr = ty; rr < 32; rr += 8)
        t[rr][tx] = in[zo + (size_t)(r0 + rr) * C + c0 + tx];
    __syncthreads();
    #pragma unroll
    for (int cc = ty; cc < 32; cc += 8) {
        __nv_bfloat16 h, l;
        split2(t[tx][cc], h, l);
        const size_t o = zo + (size_t)(c0 + cc) * R + r0 + tx;
        hi[o] = h; lo[o] = l;
    }
}

// ---------------- attention over the expert axis (E=8) ----------------
__global__ void attn_kernel(const float* __restrict__ q,
                            const float* __restrict__ kvbuf,
                            __nv_bfloat16* __restrict__ ctxh,
                            __nv_bfloat16* __restrict__ ctxl,
                            const int* __restrict__ eidPtr)
{
    const int n    = blockIdx.x;
    const int head = threadIdx.x >> 5;
    const int lane = threadIdx.x & 31;
    const int eid  = *eidPtr;

    const int hb   = head * 64 + 2 * lane;
    const float2 qv = *(const float2*)(q + n * DD + hb);
    const float* kvn = kvbuf + (size_t)n * 2 * DD;

    float s[NE];
    #pragma unroll
    for (int f = 0; f < NE; f++) {
        const float2 kv = *(const float2*)(kvn + (size_t)f * NTOK * 2 * DD + hb);
        float p = qv.x * kv.x + qv.y * kv.y;
        #pragma unroll
        for (int off = 16; off > 0; off >>= 1)
            p += __shfl_xor_sync(0xffffffffu, p, off);
        s[f] = p * 0.125f + ((f <= eid) ? 1.0f : 0.0f);
    }

    float mx = s[0];
    #pragma unroll
    for (int f = 1; f < NE; f++) mx = fmaxf(mx, s[f]);
    float sum = 0.f;
    #pragma unroll
    for (int f = 0; f < NE; f++) { s[f] = expf(s[f] - mx); sum += s[f]; }
    const float inv = 1.f / sum;

    float cx = 0.f, cy = 0.f;
    #pragma unroll
    for (int f = 0; f < NE; f++) {
        const float2 vv = *(const float2*)(kvn + (size_t)f * NTOK * 2 * DD + DD + hb);
        const float p = s[f] * inv;
        cx += p * vv.x; cy += p * vv.y;
    }
    __nv_bfloat16 hx, lx, hy, ly;
    split2(cx, hx, lx); split2(cy, hy, ly);
    __nv_bfloat162 hh; hh.x = hx; hh.y = hy;
    __nv_bfloat162 ll; ll.x = lx; ll.y = ly;
    *(__nv_bfloat162*)(ctxh + n * DD + hb) = hh;
    *(__nv_bfloat162*)(ctxl + n * DD + hb) = ll;
}

// -----------------------------------------------------------------------------
extern "C" void kernel_launch(void* const* d_in, const int* in_sizes, int n_in,
                              void* d_out, int out_size)
{
    const float* x  = (const float*)d_in[0];
    const float* W1 = (const float*)d_in[1];
    const float* b1 = (const float*)d_in[2];
    const float* W2 = (const float*)d_in[3];
    const float* b2 = (const float*)d_in[4];
    const float* Wq = (const float*)d_in[5];
    const float* bq = (const float*)d_in[6];
    const float* Wk = (const float*)d_in[7];
    const float* bk = (const float*)d_in[8];
    const float* Wv = (const float*)d_in[9];
    const float* bv = (const float*)d_in[10];
    const float* Wo = (const float*)d_in[11];
    const float* bo = (const float*)d_in[12];
    const int*  eid = (const int*)  d_in[13];

    __nv_bfloat16 *xh, *xl, *w1h, *w1l, *w2h, *w2l;
    __nv_bfloat16 *wqh, *wql, *wkvh, *wkvl, *woh, *wol;
    __nv_bfloat16 *hidh, *hidl, *eoh, *eol, *cxh, *cxl;
    float *kvb, *qb, *bkv;
    cudaGetSymbolAddress((void**)&xh,  g_xh);  cudaGetSymbolAddress((void**)&xl,  g_xl);
    cudaGetSymbolAddress((void**)&w1h, g_w1h); cudaGetSymbolAddress((void**)&w1l, g_w1l);
    cudaGetSymbolAddress((void**)&w2h, g_w2h); cudaGetSymbolAddress((void**)&w2l, g_w2l);
    cudaGetSymbolAddress((void**)&wqh, g_wqh); cudaGetSymbolAddress((void**)&wql, g_wql);
    cudaGetSymbolAddress((void**)&wkvh, g_wkvh); cudaGetSymbolAddress((void**)&wkvl, g_wkvl);
    cudaGetSymbolAddress((void**)&woh, g_woh); cudaGetSymbolAddress((void**)&wol, g_wol);
    cudaGetSymbolAddress((void**)&hidh, g_hidh); cudaGetSymbolAddress((void**)&hidl, g_hidl);
    cudaGetSymbolAddress((void**)&eoh, g_eoh); cudaGetSymbolAddress((void**)&eol, g_eol);
    cudaGetSymbolAddress((void**)&cxh, g_cxh); cudaGetSymbolAddress((void**)&cxl, g_cxl);
    cudaGetSymbolAddress((void**)&kvb, g_kv);  cudaGetSymbolAddress((void**)&qb,  g_q);
    cudaGetSymbolAddress((void**)&bkv, g_bkv);

    cudaFuncSetAttribute(mma_gemm<0, false>, cudaFuncAttributeMaxDynamicSharedMemorySize, SMEM_BYTES);
    cudaFuncSetAttribute(mma_gemm<1, false>, cudaFuncAttributeMaxDynamicSharedMemorySize, SMEM_BYTES);
    cudaFuncSetAttribute(mma_gemm<1, true>,  cudaFuncAttributeMaxDynamicSharedMemorySize, SMEM_BYTES);

    // ---- conversions ----
    k_split<<<(NTOK * DD / 4 + 255) / 256, 256>>>(x, xh, xl, NTOK * DD / 4);
    k_split<<<(DD * DD / 4 + 255) / 256, 256>>>(Wq, wqh, wql, DD * DD / 4);
    k_split<<<(DD * DD / 4 + 255) / 256, 256>>>(Wk, wkvh, wkvl, DD * DD / 4);
    k_split<<<(DD * DD / 4 + 255) / 256, 256>>>(Wv, wkvh + DD * DD, wkvl + DD * DD, DD * DD / 4);
    k_split<<<(DD * DD / 4 + 255) / 256, 256>>>(Wo, woh, wol, DD * DD / 4);
    k_cat_bias<<<4, 256>>>(bk, bv, bkv);
    {   // W1 [E,512,2048] -> [E,2048,512]
        dim3 g(DFF / 32, DD / 32, NE), b(32, 8);
        k_tsplit<<<g, b>>>(W1, w1h, w1l, DD, DFF);
    }
    {   // W2 [E,2048,512] -> [E,512,2048]
        dim3 g(DD / 32, DFF / 32, NE), b(32, 8);
        k_tsplit<<<g, b>>>(W2, w2h, w2l, DFF, DD);
    }

    // ---- FFN1: hidden[e] = relu(x @ W1[e] + b1[e])  M=4096, N=2048, K=512 ----
    mma_gemm<1, true><<<dim3(DFF / 128, NTOK / 64, NE), 256, SMEM_BYTES>>>(
        xh, xl, w1h, w1l, b1, nullptr, hidh, hidl,
        DFF, DD, 0, (size_t)DFF * DD, DFF, (size_t)NTOK * DFF, nullptr, 0);

    // ---- FFN2: eo[e] = hidden[e] @ W2[e] + b2[e]  N=512, K=2048 ----
    mma_gemm<1, false><<<dim3(DD / 128, NTOK / 64, NE), 256, SMEM_BYTES>>>(
        hidh, hidl, w2h, w2l, b2, nullptr, eoh, eol,
        DD, DFF, (size_t)NTOK * DFF, (size_t)DD * DFF, DD, (size_t)NTOK * DD, nullptr, 0);

    // ---- KV proj (fused): kv[e] = eo[e] @ [Wk;Wv]^T + [bk;bv]  N=1024, K=512 ----
    mma_gemm<0, false><<<dim3(2 * DD / 128, NTOK / 64, NE), 256, SMEM_BYTES>>>(
        eoh, eol, wkvh, wkvl, bkv, kvb, nullptr, nullptr,
        2 * DD, DD, (size_t)NTOK * DD, 0, 0, (size_t)NTOK * 2 * DD, nullptr, 0);

    // ---- Q proj (expert_id slice only) ----
    mma_gemm<0, false><<<dim3(DD / 128, NTOK / 64, 1), 256, SMEM_BYTES>>>(
        eoh, eol, wqh, wql, bq, qb, nullptr, nullptr,
        DD, DD, 0, 0, 0, 0, eid, (size_t)NTOK * DD);

    // ---- attention over experts ----
    attn_kernel<<<NTOK, 256>>>(qb, kvb, cxh, cxl, eid);

    // ---- out proj: d_out = ctx @ Wo^T + bo ----
    mma_gemm<0, false><<<dim3(DD / 128, NTOK / 64, 1), 256, SMEM_BYTES>>>(
        cxh, cxl, woh, wol, bo, (float*)d_out, nullptr, nullptr,
        DD, DD, 0, 0, 0, 0, nullptr, 0);
}

// round 6
// speedup vs baseline: 2.1045x; 1.0630x over previous
#include <cuda_runtime.h>
#include <cuda_bf16.h>

typedef unsigned int u32;
typedef unsigned long long u64;

#define NE   8
#define DD   512
#define DFF  2048
#define NTOK 4096

// ---------------- device scratch (no allocation allowed) ----------------
__device__ __nv_bfloat16 g_xh[(size_t)NTOK*DD],      g_xl[(size_t)NTOK*DD];
__device__ __nv_bfloat16 g_w1h[(size_t)NE*DFF*DD],   g_w1l[(size_t)NE*DFF*DD];   // W1^T per expert [2048,512]
__device__ __nv_bfloat16 g_w2h[(size_t)NE*DD*DFF],   g_w2l[(size_t)NE*DD*DFF];   // W2^T per expert [512,2048]
__device__ __nv_bfloat16 g_wqh[DD*DD], g_wql[DD*DD];
__device__ __nv_bfloat16 g_wkvh[2*DD*DD], g_wkvl[2*DD*DD];   // [Wk;Wv] rows concat -> [1024,512]
__device__ __nv_bfloat16 g_woh[DD*DD], g_wol[DD*DD];
__device__ float g_bkv[2*DD];
__device__ __nv_bfloat16 g_hidh[(size_t)NE*NTOK*DFF], g_hidl[(size_t)NE*NTOK*DFF];
__device__ __nv_bfloat16 g_eoh[(size_t)NE*NTOK*DD],   g_eol[(size_t)NE*NTOK*DD];
__device__ float g_kv[(size_t)NE*NTOK*2*DD];   // [e][tok][0:512]=k, [512:1024]=v
__device__ float g_q[(size_t)NTOK*DD];
__device__ __nv_bfloat16 g_cxh[(size_t)NTOK*DD], g_cxl[(size_t)NTOK*DD];

// ---------------- helpers ----------------
__device__ __forceinline__ u32 smem_u32(const void* p) {
    return (u32)__cvta_generic_to_shared(p);
}
__device__ __forceinline__ void cpa16(u32 dst, const void* src) {
    asm volatile("cp.async.cg.shared.global [%0], [%1], 16;" :: "r"(dst), "l"(src));
}
#define CPA_COMMIT() asm volatile("cp.async.commit_group;" ::: "memory")
#define CPA_WAIT1()  asm volatile("cp.async.wait_group 1;" ::: "memory")

__device__ __forceinline__ void ldsm_x4(u32* r, u32 addr) {
    asm volatile("ldmatrix.sync.aligned.m8n8.x4.shared.b16 {%0,%1,%2,%3}, [%4];"
                 : "=r"(r[0]), "=r"(r[1]), "=r"(r[2]), "=r"(r[3]) : "r"(addr));
}
__device__ __forceinline__ void ldsm_x2(u32* r, u32 addr) {
    asm volatile("ldmatrix.sync.aligned.m8n8.x2.shared.b16 {%0,%1}, [%2];"
                 : "=r"(r[0]), "=r"(r[1]) : "r"(addr));
}
__device__ __forceinline__ void mma16816(float* c, const u32* a, const u32* b) {
    asm volatile(
        "mma.sync.aligned.m16n8k16.row.col.f32.bf16.bf16.f32 "
        "{%0,%1,%2,%3}, {%4,%5,%6,%7}, {%8,%9}, {%0,%1,%2,%3};"
        : "+f"(c[0]), "+f"(c[1]), "+f"(c[2]), "+f"(c[3])
        : "r"(a[0]), "r"(a[1]), "r"(a[2]), "r"(a[3]), "r"(b[0]), "r"(b[1]));
}
__device__ __forceinline__ void split2(float v, __nv_bfloat16& h, __nv_bfloat16& l) {
    h = __float2bfloat16(v);
    l = __float2bfloat16(v - __bfloat162float(h));
}

// smem geometry: tile 128x128, ktile 32 (64B/row + 16 pad = 80B rows)
#define KTILE   32
#define ROWB    80
#define OFF_AH  0
#define OFF_AL  (128*ROWB)           // 10240
#define OFF_BH  (2*128*ROWB)         // 20480
#define OFF_BL  (3*128*ROWB)         // 30720
#define STAGEB  (4*128*ROWB)         // 40960
#define NSTAGE  2
#define SMEM_BYTES (NSTAGE * STAGEB) // 81920 -> 2 CTAs/SM

// ---------------- bf16x3 mma.sync GEMM ----------------
// D[m,n] = sum_k A[m,k]*B[n,k] + bias[n]; A,B split bf16 (hi,lo), K-major rows.
// Block tile 128x128, 8 warps (2x4), warp tile 64x32, double-buffered cp.async,
// 2 CTAs/SM. OUTMODE: 0 -> fp32 Cf ; 1 -> split bf16 Chi/Clo.
template<int OUTMODE, bool RELU>
__global__ void __launch_bounds__(256, 2) mma_gemm(
    const __nv_bfloat16* __restrict__ Ahi, const __nv_bfloat16* __restrict__ Alo,
    const __nv_bfloat16* __restrict__ Bhi, const __nv_bfloat16* __restrict__ Blo,
    const float* __restrict__ biasg,
    float* __restrict__ Cf,
    __nv_bfloat16* __restrict__ Chi, __nv_bfloat16* __restrict__ Clo,
    int N, int K,
    size_t sA, size_t sB, size_t sBias, size_t sC,
    const int* __restrict__ eidPtr, size_t eidStride)
{
    extern __shared__ __align__(128) char sm[];
    const int tid  = threadIdx.x;
    const int lane = tid & 31;
    const int wid  = tid >> 5;
    const int e    = blockIdx.z;
    const int m0   = blockIdx.y * 128;
    const int n0   = blockIdx.x * 128;

    size_t aoff = (size_t)e * sA;
    if (eidPtr) aoff += (size_t)(*eidPtr) * eidStride;
    const __nv_bfloat16* pAh = Ahi + aoff;
    const __nv_bfloat16* pAl = Alo + aoff;
    const __nv_bfloat16* pBh = Bhi + (size_t)e * sB;
    const __nv_bfloat16* pBl = Blo + (size_t)e * sB;
    const float* bias = biasg + (size_t)e * sBias;

    const u32 smb = smem_u32(sm);

    // ---- loader mapping: 128 rows x 64B, 2 threads/row, each thread 2x16B per slab ----
    const int lr = tid >> 1;
    const int lc = (tid & 1) * 2;     // chunk base 0 or 2 -> bytes 0/32; +16 covers 16/48
    const __nv_bfloat16* gAh = pAh + (size_t)(m0 + lr) * K + lc * 8;
    const __nv_bfloat16* gAl = pAl + (size_t)(m0 + lr) * K + lc * 8;
    const __nv_bfloat16* gBh = pBh + (size_t)(n0 + lr) * K + lc * 8;
    const __nv_bfloat16* gBl = pBl + (size_t)(n0 + lr) * K + lc * 8;
    const u32 so = (u32)(lr * ROWB + lc * 16);

    // ---- warp/compute mapping: warps 2x4, warp tile 64x32 ----
    const int wm = wid >> 2;       // 0..1 -> m offset 0/64
    const int wn = wid & 3;        // 0..3 -> n offset 0/32/64/96

    u32 offA[4][2], offB[4][2];
    {
        const int rA = wm * 64 + (lane & 15);
        const int cA = lane >> 4;
        #pragma unroll
        for (int im = 0; im < 4; im++)
            #pragma unroll
            for (int ks = 0; ks < 2; ks++)
                offA[im][ks] = (u32)((rA + im * 16) * ROWB + (ks * 2 + cA) * 16);
        const int rB = wn * 32 + (lane & 7);
        const int cB = (lane >> 3) & 1;
        #pragma unroll
        for (int in = 0; in < 4; in++)
            #pragma unroll
            for (int ks = 0; ks < 2; ks++)
                offB[in][ks] = (u32)((rB + in * 8) * ROWB + (ks * 2 + cB) * 16);
    }

    float acc[4][4][4];
    #pragma unroll
    for (int im = 0; im < 4; im++)
        #pragma unroll
        for (int in = 0; in < 4; in++)
            #pragma unroll
            for (int q = 0; q < 4; q++) acc[im][in][q] = 0.f;

    const int nt = K >> 5;

    // ---- prologue: fill both stages ----
    #pragma unroll
    for (int p = 0; p < 2; p++) {
        const int k0 = p * KTILE;
        const u32 b = smb + p * STAGEB;
        cpa16(b + OFF_AH + so,      gAh + k0);
        cpa16(b + OFF_AH + so + 16, gAh + k0 + 8);
        cpa16(b + OFF_AL + so,      gAl + k0);
        cpa16(b + OFF_AL + so + 16, gAl + k0 + 8);
        cpa16(b + OFF_BH + so,      gBh + k0);
        cpa16(b + OFF_BH + so + 16, gBh + k0 + 8);
        cpa16(b + OFF_BL + so,      gBl + k0);
        cpa16(b + OFF_BL + so + 16, gBl + k0 + 8);
        CPA_COMMIT();
    }

    for (int i = 0; i < nt; i++) {
        CPA_WAIT1();          // tile i resident
        __syncthreads();

        const u32 stage = smb + (u32)(i & 1) * STAGEB;
        #pragma unroll
        for (int ks = 0; ks < 2; ks++) {
            u32 ah[4][4], al[4][4];
            #pragma unroll
            for (int im = 0; im < 4; im++) {
                ldsm_x4(ah[im], stage + OFF_AH + offA[im][ks]);
                ldsm_x4(al[im], stage + OFF_AL + offA[im][ks]);
            }
            u32 bh[4][2], bl[4][2];
            #pragma unroll
            for (int in = 0; in < 4; in++) {
                ldsm_x2(bh[in], stage + OFF_BH + offB[in][ks]);
                ldsm_x2(bl[in], stage + OFF_BL + offB[in][ks]);
            }
            #pragma unroll
            for (int im = 0; im < 4; im++)
                #pragma unroll
                for (int in = 0; in < 4; in++) {
                    mma16816(acc[im][in], ah[im], bh[in]);
                    mma16816(acc[im][in], ah[im], bl[in]);
                    mma16816(acc[im][in], al[im], bh[in]);
                }
        }
        __syncthreads();      // all warps done reading slot i&1

        const int inext = i + 2;
        if (inext < nt) {
            const int k0 = inext * KTILE;
            const u32 b = smb + (u32)(i & 1) * STAGEB;
            cpa16(b + OFF_AH + so,      gAh + k0);
            cpa16(b + OFF_AH + so + 16, gAh + k0 + 8);
            cpa16(b + OFF_AL + so,      gAl + k0);
            cpa16(b + OFF_AL + so + 16, gAl + k0 + 8);
            cpa16(b + OFF_BH + so,      gBh + k0);
            cpa16(b + OFF_BH + so + 16, gBh + k0 + 8);
            cpa16(b + OFF_BL + so,      gBl + k0);
            cpa16(b + OFF_BL + so + 16, gBl + k0 + 8);
        }
        CPA_COMMIT();         // uniform group accounting
    }

    // ---- epilogue ----
    const int g = lane >> 2;
    const int cb_in = (lane & 3) * 2;
    #pragma unroll
    for (int in = 0; in < 4; in++) {
        const int col = n0 + wn * 32 + in * 8 + cb_in;
        const float bx = bias[col], by = bias[col + 1];
        #pragma unroll
        for (int im = 0; im < 4; im++) {
            const int r0 = m0 + wm * 64 + im * 16 + g;
            const int r1 = r0 + 8;
            float v00 = acc[im][in][0] + bx, v01 = acc[im][in][1] + by;
            float v10 = acc[im][in][2] + bx, v11 = acc[im][in][3] + by;
            if (RELU) {
                v00 = fmaxf(v00, 0.f); v01 = fmaxf(v01, 0.f);
                v10 = fmaxf(v10, 0.f); v11 = fmaxf(v11, 0.f);
            }
            if (OUTMODE == 0) {
                float* o = Cf + (size_t)e * sC;
                float2 a0 = {v00, v01}, a1 = {v10, v11};
                *(float2*)(o + (size_t)r0 * N + col) = a0;
                *(float2*)(o + (size_t)r1 * N + col) = a1;
            } else {
                __nv_bfloat16 h00, l00, h01, l01, h10, l10, h11, l11;
                split2(v00, h00, l00); split2(v01, h01, l01);
                split2(v10, h10, l10); split2(v11, h11, l11);
                __nv_bfloat16* oh = Chi + (size_t)e * sC;
                __nv_bfloat16* ol = Clo + (size_t)e * sC;
                __nv_bfloat162 p;
                p.x = h00; p.y = h01; *(__nv_bfloat162*)(oh + (size_t)r0 * N + col) = p;
                p.x = l00; p.y = l01; *(__nv_bfloat162*)(ol + (size_t)r0 * N + col) = p;
                p.x = h10; p.y = h11; *(__nv_bfloat162*)(oh + (size_t)r1 * N + col) = p;
                p.x = l10; p.y = l11; *(__nv_bfloat162*)(ol + (size_t)r1 * N + col) = p;
            }
        }
    }
}

// ---------------- conversion kernels ----------------
__global__ void k_split(const float* __restrict__ in,
                        __nv_bfloat16* __restrict__ hi, __nv_bfloat16* __restrict__ lo,
                        int n4)
{
    const int i = blockIdx.x * 256 + threadIdx.x;
    if (i >= n4) return;
    const float4 u = ((const float4*)in)[i];
    __nv_bfloat16 h[4], l[4];
    split2(u.x, h[0], l[0]); split2(u.y, h[1], l[1]);
    split2(u.z, h[2], l[2]); split2(u.w, h[3], l[3]);
    ((uint2*)hi)[i] = *(const uint2*)h;
    ((uint2*)lo)[i] = *(const uint2*)l;
}

__global__ void k_cat_bias(const float* __restrict__ a, const float* __restrict__ b,
                           float* __restrict__ o)
{
    const int i = threadIdx.x + blockIdx.x * 256;
    if (i < DD) o[i] = a[i];
    else if (i < 2 * DD) o[i] = b[i - DD];
}

// transpose + split: in [R,C] fp32 (batched over z) -> out [C,R] bf16 hi/lo
__global__ void k_tsplit(const float* __restrict__ in,
                         __nv_bfloat16* __restrict__ hi, __nv_bfloat16* __restrict__ lo,
                         int R, int C)
{
    __shared__ float t[32][33];
    const size_t zo = (size_t)blockIdx.z * R * C;
    const int c0 = blockIdx.x * 32, r0 = blockIdx.y * 32;
    const int tx = threadIdx.x, ty = threadIdx.y;
    #pragma unroll
    for (int rr = ty; rr < 32; rr += 8)
        t[rr][tx] = in[zo + (size_t)(r0 + rr) * C + c0 + tx];
    __syncthreads();
    #pragma unroll
    for (int cc = ty; cc < 32; cc += 8) {
        __nv_bfloat16 h, l;
        split2(t[tx][cc], h, l);
        const size_t o = zo + (size_t)(c0 + cc) * R + r0 + tx;
        hi[o] = h; lo[o] = l;
    }
}

// ---------------- attention over the expert axis (E=8) ----------------
__global__ void attn_kernel(const float* __restrict__ q,
                            const float* __restrict__ kvbuf,
                            __nv_bfloat16* __restrict__ ctxh,
                            __nv_bfloat16* __restrict__ ctxl,
                            const int* __restrict__ eidPtr)
{
    const int n    = blockIdx.x;
    const int head = threadIdx.x >> 5;
    const int lane = threadIdx.x & 31;
    const int eid  = *eidPtr;

    const int hb   = head * 64 + 2 * lane;
    const float2 qv = *(const float2*)(q + n * DD + hb);
    const float* kvn = kvbuf + (size_t)n * 2 * DD;

    float s[NE];
    #pragma unroll
    for (int f = 0; f < NE; f++) {
        const float2 kv = *(const float2*)(kvn + (size_t)f * NTOK * 2 * DD + hb);
        float p = qv.x * kv.x + qv.y * kv.y;
        #pragma unroll
        for (int off = 16; off > 0; off >>= 1)
            p += __shfl_xor_sync(0xffffffffu, p, off);
        s[f] = p * 0.125f + ((f <= eid) ? 1.0f : 0.0f);
    }

    float mx = s[0];
    #pragma unroll
    for (int f = 1; f < NE; f++) mx = fmaxf(mx, s[f]);
    float sum = 0.f;
    #pragma unroll
    for (int f = 0; f < NE; f++) { s[f] = expf(s[f] - mx); sum += s[f]; }
    const float inv = 1.f / sum;

    float cx = 0.f, cy = 0.f;
    #pragma unroll
    for (int f = 0; f < NE; f++) {
        const float2 vv = *(const float2*)(kvn + (size_t)f * NTOK * 2 * DD + DD + hb);
        const float p = s[f] * inv;
        cx += p * vv.x; cy += p * vv.y;
    }
    __nv_bfloat16 hx, lx, hy, ly;
    split2(cx, hx, lx); split2(cy, hy, ly);
    __nv_bfloat162 hh; hh.x = hx; hh.y = hy;
    __nv_bfloat162 ll; ll.x = lx; ll.y = ly;
    *(__nv_bfloat162*)(ctxh + n * DD + hb) = hh;
    *(__nv_bfloat162*)(ctxl + n * DD + hb) = ll;
}

// -----------------------------------------------------------------------------
extern "C" void kernel_launch(void* const* d_in, const int* in_sizes, int n_in,
                              void* d_out, int out_size)
{
    const float* x  = (const float*)d_in[0];
    const float* W1 = (const float*)d_in[1];
    const float* b1 = (const float*)d_in[2];
    const float* W2 = (const float*)d_in[3];
    const float* b2 = (const float*)d_in[4];
    const float* Wq = (const float*)d_in[5];
    const float* bq = (const float*)d_in[6];
    const float* Wk = (const float*)d_in[7];
    const float* bk = (const float*)d_in[8];
    const float* Wv = (const float*)d_in[9];
    const float* bv = (const float*)d_in[10];
    const float* Wo = (const float*)d_in[11];
    const float* bo = (const float*)d_in[12];
    const int*  eid = (const int*)  d_in[13];

    __nv_bfloat16 *xh, *xl, *w1h, *w1l, *w2h, *w2l;
    __nv_bfloat16 *wqh, *wql, *wkvh, *wkvl, *woh, *wol;
    __nv_bfloat16 *hidh, *hidl, *eoh, *eol, *cxh, *cxl;
    float *kvb, *qb, *bkv;
    cudaGetSymbolAddress((void**)&xh,  g_xh);  cudaGetSymbolAddress((void**)&xl,  g_xl);
    cudaGetSymbolAddress((void**)&w1h, g_w1h); cudaGetSymbolAddress((void**)&w1l, g_w1l);
    cudaGetSymbolAddress((void**)&w2h, g_w2h); cudaGetSymbolAddress((void**)&w2l, g_w2l);
    cudaGetSymbolAddress((void**)&wqh, g_wqh); cudaGetSymbolAddress((void**)&wql, g_wql);
    cudaGetSymbolAddress((void**)&wkvh, g_wkvh); cudaGetSymbolAddress((void**)&wkvl, g_wkvl);
    cudaGetSymbolAddress((void**)&woh, g_woh); cudaGetSymbolAddress((void**)&wol, g_wol);
    cudaGetSymbolAddress((void**)&hidh, g_hidh); cudaGetSymbolAddress((void**)&hidl, g_hidl);
    cudaGetSymbolAddress((void**)&eoh, g_eoh); cudaGetSymbolAddress((void**)&eol, g_eol);
    cudaGetSymbolAddress((void**)&cxh, g_cxh); cudaGetSymbolAddress((void**)&cxl, g_cxl);
    cudaGetSymbolAddress((void**)&kvb, g_kv);  cudaGetSymbolAddress((void**)&qb,  g_q);
    cudaGetSymbolAddress((void**)&bkv, g_bkv);

    cudaFuncSetAttribute(mma_gemm<0, false>, cudaFuncAttributeMaxDynamicSharedMemorySize, SMEM_BYTES);
    cudaFuncSetAttribute(mma_gemm<1, false>, cudaFuncAttributeMaxDynamicSharedMemorySize, SMEM_BYTES);
    cudaFuncSetAttribute(mma_gemm<1, true>,  cudaFuncAttributeMaxDynamicSharedMemorySize, SMEM_BYTES);

    // ---- conversions needed by FFN1 (launches 1-5; FFN1 is launch 6 for ncu -s 5) ----
    k_split<<<(NTOK * DD / 4 + 255) / 256, 256>>>(x, xh, xl, NTOK * DD / 4);        // 1
    {   // 2: W1 [E,512,2048] -> [E,2048,512]
        dim3 g(DFF / 32, DD / 32, NE), b(32, 8);
        k_tsplit<<<g, b>>>(W1, w1h, w1l, DD, DFF);
    }
    {   // 3: W2 [E,2048,512] -> [E,512,2048]
        dim3 g(DD / 32, DFF / 32, NE), b(32, 8);
        k_tsplit<<<g, b>>>(W2, w2h, w2l, DFF, DD);
    }
    k_split<<<(DD * DD / 4 + 255) / 256, 256>>>(Wq, wqh, wql, DD * DD / 4);         // 4
    k_split<<<(DD * DD / 4 + 255) / 256, 256>>>(Wk, wkvh, wkvl, DD * DD / 4);       // 5

    // ---- 6: FFN1: hidden[e] = relu(x @ W1[e] + b1[e])  M=4096, N=2048, K=512 ----
    mma_gemm<1, true><<<dim3(DFF / 128, NTOK / 128, NE), 256, SMEM_BYTES>>>(
        xh, xl, w1h, w1l, b1, nullptr, hidh, hidl,
        DFF, DD, 0, (size_t)DFF * DD, DFF, (size_t)NTOK * DFF, nullptr, 0);

    // ---- remaining conversions (needed from KV proj onward) ----
    k_split<<<(DD * DD / 4 + 255) / 256, 256>>>(Wv, wkvh + DD * DD, wkvl + DD * DD, DD * DD / 4);
    k_split<<<(DD * DD / 4 + 255) / 256, 256>>>(Wo, woh, wol, DD * DD / 4);
    k_cat_bias<<<4, 256>>>(bk, bv, bkv);

    // ---- FFN2: eo[e] = hidden[e] @ W2[e] + b2[e]  N=512, K=2048 ----
    mma_gemm<1, false><<<dim3(DD / 128, NTOK / 128, NE), 256, SMEM_BYTES>>>(
        hidh, hidl, w2h, w2l, b2, nullptr, eoh, eol,
        DD, DFF, (size_t)NTOK * DFF, (size_t)DD * DFF, DD, (size_t)NTOK * DD, nullptr, 0);

    // ---- KV proj (fused): kv[e] = eo[e] @ [Wk;Wv]^T + [bk;bv]  N=1024, K=512 ----
    mma_gemm<0, false><<<dim3(2 * DD / 128, NTOK / 128, NE), 256, SMEM_BYTES>>>(
        eoh, eol, wkvh, wkvl, bkv, kvb, nullptr, nullptr,
        2 * DD, DD, (size_t)NTOK * DD, 0, 0, (size_t)NTOK * 2 * DD, nullptr, 0);

    // ---- Q proj (expert_id slice only) ----
    mma_gemm<0, false><<<dim3(DD / 128, NTOK / 128, 1), 256, SMEM_BYTES>>>(
        eoh, eol, wqh, wql, bq, qb, nullptr, nullptr,
        DD, DD, 0, 0, 0, 0, eid, (size_t)NTOK * DD);

    // ---- attention over experts ----
    attn_kernel<<<NTOK, 256>>>(qb, kvb, cxh, cxl, eid);

    // ---- out proj: d_out = ctx @ Wo^T + bo ----
    mma_gemm<0, false><<<dim3(DD / 128, NTOK / 128, 1), 256, SMEM_BYTES>>>(
        cxh, cxl, woh, wol, bo, (float*)d_out, nullptr, nullptr,
        DD, DD, 0, 0, 0, 0, nullptr, 0);
}

// round 7
// speedup vs baseline: 5.0039x; 2.3777x over previous
#include <cuda_runtime.h>
#include <cuda_fp16.h>

typedef unsigned int u32;
typedef unsigned long long u64;

#define NE   8
#define DD   512
#define DFF  2048
#define NTOK 4096

// ---------------- device scratch (no allocation allowed) ----------------
__device__ __half g_x  [(size_t)NTOK*DD];
__device__ __half g_w1 [(size_t)NE*DFF*DD];     // W1^T per expert [2048,512]
__device__ __half g_w2 [(size_t)NE*DD*DFF];     // W2^T per expert [512,2048]
__device__ __half g_wq [DD*DD];
__device__ __half g_wkv[2*DD*DD];               // [Wk;Wv] rows concat -> [1024,512]
__device__ __half g_wo [DD*DD];
__device__ float  g_bkv[2*DD];
__device__ __half g_hid[(size_t)NE*NTOK*DFF];
__device__ __half g_eo [(size_t)NE*NTOK*DD];
__device__ float  g_kv [(size_t)NE*NTOK*2*DD];  // [e][tok][0:512]=k, [512:1024]=v
__device__ float  g_q  [(size_t)NTOK*DD];
__device__ __half g_cx [(size_t)NTOK*DD];

// ---------------- helpers ----------------
__device__ __forceinline__ u32 smem_u32(const void* p) {
    return (u32)__cvta_generic_to_shared(p);
}
__device__ __forceinline__ void cpa16(u32 dst, const void* src) {
    asm volatile("cp.async.cg.shared.global [%0], [%1], 16;" :: "r"(dst), "l"(src));
}
#define CPA_COMMIT() asm volatile("cp.async.commit_group;" ::: "memory")
#define CPA_WAIT1()  asm volatile("cp.async.wait_group 1;" ::: "memory")

__device__ __forceinline__ void ldsm_x4(u32* r, u32 addr) {
    asm volatile("ldmatrix.sync.aligned.m8n8.x4.shared.b16 {%0,%1,%2,%3}, [%4];"
                 : "=r"(r[0]), "=r"(r[1]), "=r"(r[2]), "=r"(r[3]) : "r"(addr));
}
__device__ __forceinline__ void ldsm_x2(u32* r, u32 addr) {
    asm volatile("ldmatrix.sync.aligned.m8n8.x2.shared.b16 {%0,%1}, [%2];"
                 : "=r"(r[0]), "=r"(r[1]) : "r"(addr));
}
__device__ __forceinline__ void mma16816(float* c, const u32* a, const u32* b) {
    asm volatile(
        "mma.sync.aligned.m16n8k16.row.col.f32.f16.f16.f32 "
        "{%0,%1,%2,%3}, {%4,%5,%6,%7}, {%8,%9}, {%0,%1,%2,%3};"
        : "+f"(c[0]), "+f"(c[1]), "+f"(c[2]), "+f"(c[3])
        : "r"(a[0]), "r"(a[1]), "r"(a[2]), "r"(a[3]), "r"(b[0]), "r"(b[1]));
}

// smem geometry: tile 128x128, ktile 32 (64B/row + 16 pad = 80B rows), slabs A,B
#define KTILE   32
#define ROWB    80
#define OFF_A   0
#define OFF_B   (128*ROWB)           // 10240
#define STAGEB  (2*128*ROWB)         // 20480
#define NSTAGE  2
#define SMEM_BYTES (NSTAGE * STAGEB) // 40960

// ---------------- fp16 mma.sync GEMM ----------------
// D[m,n] = sum_k A[m,k]*B[n,k] + bias[n]; A,B fp16 K-major rows, fp32 accum.
// Block tile 128x128, 8 warps (2x4), warp tile 64x32, double-buffered cp.async.
// OUTMODE: 0 -> fp32 Cf ; 1 -> fp16 Ch.
template<int OUTMODE, bool RELU>
__global__ void __launch_bounds__(256, 2) mma_gemm(
    const __half* __restrict__ A, const __half* __restrict__ B,
    const float* __restrict__ biasg,
    float* __restrict__ Cf, __half* __restrict__ Ch,
    int N, int K,
    size_t sA, size_t sB, size_t sBias, size_t sC,
    const int* __restrict__ eidPtr, size_t eidStride)
{
    extern __shared__ __align__(128) char sm[];
    const int tid  = threadIdx.x;
    const int lane = tid & 31;
    const int wid  = tid >> 5;
    const int e    = blockIdx.z;
    const int m0   = blockIdx.y * 128;
    const int n0   = blockIdx.x * 128;

    size_t aoff = (size_t)e * sA;
    if (eidPtr) aoff += (size_t)(*eidPtr) * eidStride;
    const __half* pA = A + aoff;
    const __half* pB = B + (size_t)e * sB;
    const float* bias = biasg + (size_t)e * sBias;

    const u32 smb = smem_u32(sm);

    // ---- loader mapping: 128 rows x 64B/slab, 2 threads/row, 2x16B per slab ----
    const int lr = tid >> 1;
    const int lc = (tid & 1) * 2;
    const __half* gA = pA + (size_t)(m0 + lr) * K + lc * 8;
    const __half* gB = pB + (size_t)(n0 + lr) * K + lc * 8;
    const u32 so = (u32)(lr * ROWB + lc * 16);

    // ---- warp/compute mapping: warps 2x4, warp tile 64x32 ----
    const int wm = wid >> 2;
    const int wn = wid & 3;

    u32 offA[4][2], offB[4][2];
    {
        const int rA = wm * 64 + (lane & 15);
        const int cA = lane >> 4;
        #pragma unroll
        for (int im = 0; im < 4; im++)
            #pragma unroll
            for (int ks = 0; ks < 2; ks++)
                offA[im][ks] = (u32)((rA + im * 16) * ROWB + (ks * 2 + cA) * 16);
        const int rB = wn * 32 + (lane & 7);
        const int cB = (lane >> 3) & 1;
        #pragma unroll
        for (int in = 0; in < 4; in++)
            #pragma unroll
            for (int ks = 0; ks < 2; ks++)
                offB[in][ks] = (u32)((rB + in * 8) * ROWB + (ks * 2 + cB) * 16);
    }

    float acc[4][4][4];
    #pragma unroll
    for (int im = 0; im < 4; im++)
        #pragma unroll
        for (int in = 0; in < 4; in++)
            #pragma unroll
            for (int q = 0; q < 4; q++) acc[im][in][q] = 0.f;

    const int nt = K >> 5;

    // ---- prologue: fill both stages ----
    #pragma unroll
    for (int p = 0; p < 2; p++) {
        const int k0 = p * KTILE;
        const u32 b = smb + p * STAGEB;
        cpa16(b + OFF_A + so,      gA + k0);
        cpa16(b + OFF_A + so + 16, gA + k0 + 8);
        cpa16(b + OFF_B + so,      gB + k0);
        cpa16(b + OFF_B + so + 16, gB + k0 + 8);
        CPA_COMMIT();
    }

    for (int i = 0; i < nt; i++) {
        CPA_WAIT1();
        __syncthreads();

        const u32 stage = smb + (u32)(i & 1) * STAGEB;
        #pragma unroll
        for (int ks = 0; ks < 2; ks++) {
            u32 a[4][4];
            #pragma unroll
            for (int im = 0; im < 4; im++)
                ldsm_x4(a[im], stage + OFF_A + offA[im][ks]);
            u32 b[4][2];
            #pragma unroll
            for (int in = 0; in < 4; in++)
                ldsm_x2(b[in], stage + OFF_B + offB[in][ks]);
            #pragma unroll
            for (int im = 0; im < 4; im++)
                #pragma unroll
                for (int in = 0; in < 4; in++)
                    mma16816(acc[im][in], a[im], b[in]);
        }
        __syncthreads();

        const int inext = i + 2;
        if (inext < nt) {
            const int k0 = inext * KTILE;
            const u32 b = smb + (u32)(i & 1) * STAGEB;
            cpa16(b + OFF_A + so,      gA + k0);
            cpa16(b + OFF_A + so + 16, gA + k0 + 8);
            cpa16(b + OFF_B + so,      gB + k0);
            cpa16(b + OFF_B + so + 16, gB + k0 + 8);
        }
        CPA_COMMIT();
    }

    // ---- epilogue ----
    const int g = lane >> 2;
    const int cb_in = (lane & 3) * 2;
    #pragma unroll
    for (int in = 0; in < 4; in++) {
        const int col = n0 + wn * 32 + in * 8 + cb_in;
        const float bx = bias[col], by = bias[col + 1];
        #pragma unroll
        for (int im = 0; im < 4; im++) {
            const int r0 = m0 + wm * 64 + im * 16 + g;
            const int r1 = r0 + 8;
            float v00 = acc[im][in][0] + bx, v01 = acc[im][in][1] + by;
            float v10 = acc[im][in][2] + bx, v11 = acc[im][in][3] + by;
            if (RELU) {
                v00 = fmaxf(v00, 0.f); v01 = fmaxf(v01, 0.f);
                v10 = fmaxf(v10, 0.f); v11 = fmaxf(v11, 0.f);
            }
            if (OUTMODE == 0) {
                float* o = Cf + (size_t)e * sC;
                float2 a0 = {v00, v01}, a1 = {v10, v11};
                *(float2*)(o + (size_t)r0 * N + col) = a0;
                *(float2*)(o + (size_t)r1 * N + col) = a1;
            } else {
                __half* oh = Ch + (size_t)e * sC;
                __half2 p;
                p.x = __float2half_rn(v00); p.y = __float2half_rn(v01);
                *(__half2*)(oh + (size_t)r0 * N + col) = p;
                p.x = __float2half_rn(v10); p.y = __float2half_rn(v11);
                *(__half2*)(oh + (size_t)r1 * N + col) = p;
            }
        }
    }
}

// ---------------- conversion kernels ----------------
__global__ void k_half(const float* __restrict__ in, __half* __restrict__ out, int n4)
{
    const int i = blockIdx.x * 256 + threadIdx.x;
    if (i >= n4) return;
    const float4 u = ((const float4*)in)[i];
    __half h[4];
    h[0] = __float2half_rn(u.x); h[1] = __float2half_rn(u.y);
    h[2] = __float2half_rn(u.z); h[3] = __float2half_rn(u.w);
    ((uint2*)out)[i] = *(const uint2*)h;
}

__global__ void k_cat_bias(const float* __restrict__ a, const float* __restrict__ b,
                           float* __restrict__ o)
{
    const int i = threadIdx.x + blockIdx.x * 256;
    if (i < DD) o[i] = a[i];
    else if (i < 2 * DD) o[i] = b[i - DD];
}

// transpose + convert: in [R,C] fp32 (batched over z) -> out [C,R] fp16
__global__ void k_thalf(const float* __restrict__ in, __half* __restrict__ out,
                        int R, int C)
{
    __shared__ float t[32][33];
    const size_t zo = (size_t)blockIdx.z * R * C;
    const int c0 = blockIdx.x * 32, r0 = blockIdx.y * 32;
    const int tx = threadIdx.x, ty = threadIdx.y;
    #pragma unroll
    for (int rr = ty; rr < 32; rr += 8)
        t[rr][tx] = in[zo + (size_t)(r0 + rr) * C + c0 + tx];
    __syncthreads();
    #pragma unroll
    for (int cc = ty; cc < 32; cc += 8)
        out[zo + (size_t)(c0 + cc) * R + r0 + tx] = __float2half_rn(t[tx][cc]);
}

// ---------------- attention over the expert axis (E=8) ----------------
__global__ void attn_kernel(const float* __restrict__ q,
                            const float* __restrict__ kvbuf,
                            __half* __restrict__ ctx,
                            const int* __restrict__ eidPtr)
{
    const int n    = blockIdx.x;
    const int head = threadIdx.x >> 5;
    const int lane = threadIdx.x & 31;
    const int eid  = *eidPtr;

    const int hb   = head * 64 + 2 * lane;
    const float2 qv = *(const float2*)(q + n * DD + hb);
    const float* kvn = kvbuf + (size_t)n * 2 * DD;

    float s[NE];
    #pragma unroll
    for (int f = 0; f < NE; f++) {
        const float2 kv = *(const float2*)(kvn + (size_t)f * NTOK * 2 * DD + hb);
        float p = qv.x * kv.x + qv.y * kv.y;
        #pragma unroll
        for (int off = 16; off > 0; off >>= 1)
            p += __shfl_xor_sync(0xffffffffu, p, off);
        s[f] = p * 0.125f + ((f <= eid) ? 1.0f : 0.0f);
    }

    float mx = s[0];
    #pragma unroll
    for (int f = 1; f < NE; f++) mx = fmaxf(mx, s[f]);
    float sum = 0.f;
    #pragma unroll
    for (int f = 0; f < NE; f++) { s[f] = expf(s[f] - mx); sum += s[f]; }
    const float inv = 1.f / sum;

    float cx = 0.f, cy = 0.f;
    #pragma unroll
    for (int f = 0; f < NE; f++) {
        const float2 vv = *(const float2*)(kvn + (size_t)f * NTOK * 2 * DD + DD + hb);
        const float p = s[f] * inv;
        cx += p * vv.x; cy += p * vv.y;
    }
    __half2 o;
    o.x = __float2half_rn(cx); o.y = __float2half_rn(cy);
    *(__half2*)(ctx + n * DD + hb) = o;
}

// -----------------------------------------------------------------------------
extern "C" void kernel_launch(void* const* d_in, const int* in_sizes, int n_in,
                              void* d_out, int out_size)
{
    const float* x  = (const float*)d_in[0];
    const float* W1 = (const float*)d_in[1];
    const float* b1 = (const float*)d_in[2];
    const float* W2 = (const float*)d_in[3];
    const float* b2 = (const float*)d_in[4];
    const float* Wq = (const float*)d_in[5];
    const float* bq = (const float*)d_in[6];
    const float* Wk = (const float*)d_in[7];
    const float* bk = (const float*)d_in[8];
    const float* Wv = (const float*)d_in[9];
    const float* bv = (const float*)d_in[10];
    const float* Wo = (const float*)d_in[11];
    const float* bo = (const float*)d_in[12];
    const int*  eid = (const int*)  d_in[13];

    __half *xh, *w1, *w2, *wq, *wkv, *wo, *hid, *eo, *cx;
    float *kvb, *qb, *bkv;
    cudaGetSymbolAddress((void**)&xh,  g_x);
    cudaGetSymbolAddress((void**)&w1,  g_w1);
    cudaGetSymbolAddress((void**)&w2,  g_w2);
    cudaGetSymbolAddress((void**)&wq,  g_wq);
    cudaGetSymbolAddress((void**)&wkv, g_wkv);
    cudaGetSymbolAddress((void**)&wo,  g_wo);
    cudaGetSymbolAddress((void**)&hid, g_hid);
    cudaGetSymbolAddress((void**)&eo,  g_eo);
    cudaGetSymbolAddress((void**)&cx,  g_cx);
    cudaGetSymbolAddress((void**)&kvb, g_kv);
    cudaGetSymbolAddress((void**)&qb,  g_q);
    cudaGetSymbolAddress((void**)&bkv, g_bkv);

    cudaFuncSetAttribute(mma_gemm<0, false>, cudaFuncAttributeMaxDynamicSharedMemorySize, SMEM_BYTES);
    cudaFuncSetAttribute(mma_gemm<1, false>, cudaFuncAttributeMaxDynamicSharedMemorySize, SMEM_BYTES);
    cudaFuncSetAttribute(mma_gemm<1, true>,  cudaFuncAttributeMaxDynamicSharedMemorySize, SMEM_BYTES);

    // ---- conversions needed by FFN1 (launches 1-5; FFN1 is launch 6 for ncu -s 5) ----
    k_half<<<(NTOK * DD / 4 + 255) / 256, 256>>>(x, xh, NTOK * DD / 4);             // 1
    {   // 2: W1 [E,512,2048] -> [E,2048,512]
        dim3 g(DFF / 32, DD / 32, NE), b(32, 8);
        k_thalf<<<g, b>>>(W1, w1, DD, DFF);
    }
    {   // 3: W2 [E,2048,512] -> [E,512,2048]
        dim3 g(DD / 32, DFF / 32, NE), b(32, 8);
        k_thalf<<<g, b>>>(W2, w2, DFF, DD);
    }
    k_half<<<(DD * DD / 4 + 255) / 256, 256>>>(Wq, wq, DD * DD / 4);                // 4
    k_half<<<(DD * DD / 4 + 255) / 256, 256>>>(Wk, wkv, DD * DD / 4);               // 5

    // ---- 6: FFN1: hidden[e] = relu(x @ W1[e] + b1[e])  M=4096, N=2048, K=512 ----
    mma_gemm<1, true><<<dim3(DFF / 128, NTOK / 128, NE), 256, SMEM_BYTES>>>(
        xh, w1, b1, nullptr, hid,
        DFF, DD, 0, (size_t)DFF * DD, DFF, (size_t)NTOK * DFF, nullptr, 0);

    // ---- remaining conversions ----
    k_half<<<(DD * DD / 4 + 255) / 256, 256>>>(Wv, wkv + DD * DD, DD * DD / 4);
    k_half<<<(DD * DD / 4 + 255) / 256, 256>>>(Wo, wo, DD * DD / 4);
    k_cat_bias<<<4, 256>>>(bk, bv, bkv);

    // ---- FFN2: eo[e] = hidden[e] @ W2[e] + b2[e]  N=512, K=2048 ----
    mma_gemm<1, false><<<dim3(DD / 128, NTOK / 128, NE), 256, SMEM_BYTES>>>(
        hid, w2, b2, nullptr, eo,
        DD, DFF, (size_t)NTOK * DFF, (size_t)DD * DFF, DD, (size_t)NTOK * DD, nullptr, 0);

    // ---- KV proj (fused): kv[e] = eo[e] @ [Wk;Wv]^T + [bk;bv]  N=1024, K=512 ----
    mma_gemm<0, false><<<dim3(2 * DD / 128, NTOK / 128, NE), 256, SMEM_BYTES>>>(
        eo, wkv, bkv, kvb, nullptr,
        2 * DD, DD, (size_t)NTOK * DD, 0, 0, (size_t)NTOK * 2 * DD, nullptr, 0);

    // ---- Q proj (expert_id slice only) ----
    mma_gemm<0, false><<<dim3(DD / 128, NTOK / 128, 1), 256, SMEM_BYTES>>>(
        eo, wq, bq, qb, nullptr,
        DD, DD, 0, 0, 0, 0, eid, (size_t)NTOK * DD);

    // ---- attention over experts ----
    attn_kernel<<<NTOK, 256>>>(qb, kvb, cx, eid);

    // ---- out proj: d_out = ctx @ Wo^T + bo ----
    mma_gemm<0, false><<<dim3(DD / 128, NTOK / 128, 1), 256, SMEM_BYTES>>>(
        cx, wo, bo, (float*)d_out, nullptr,
        DD, DD, 0, 0, 0, 0, nullptr, 0);
}